// round 2
// baseline (speedup 1.0000x reference)
#include <cuda_runtime.h>
#include <math_constants.h>

// Problem constants
#define FRAMES (32 * 512)   // B*N = 16384
#define DMODEL 512
#define DHTOT  1176         // DEPTH*HEADS = 147*8
#define QKW_N  2352         // 2*DHTOT

// Scratch: device globals (no cudaMalloc allowed)
__device__ float g_qk[(size_t)FRAMES * QKW_N];  // combined q|k projection
__device__ float g_v [(size_t)FRAMES * DHTOT];  // v projection (updated in place by attention)

// ---------------------------------------------------------------------------
// Tiled fp32 SGEMM: C[M,N] = A[M,K] @ B[K,N] (+ bias[N])
// BM=128, BN=128, BK=8, 256 threads, 8x8 microtile per thread.
// Double-buffered shared tiles: prefetch tile kt+BK into registers while
// computing on tile kt, store into the alternate buffer, one barrier/iter.
// Requirements satisfied by all 3 calls: M % 128 == 0, K % 8 == 0, N % 4 == 0.
// N edge (2352, 1176) handled by per-float4 predication.
// ---------------------------------------------------------------------------
__global__ __launch_bounds__(256, 2)
void sgemm_kernel(const float* __restrict__ A, const float* __restrict__ B,
                  float* __restrict__ C, const float* __restrict__ bias,
                  int M, int N, int K)
{
    constexpr int BM = 128, BN = 128, BK = 8;
    __shared__ float As[2][BK][BM];   // transposed A tile
    __shared__ float Bs[2][BK][BN];

    const int tid = threadIdx.x;
    const int m0 = blockIdx.y * BM;
    const int n0 = blockIdx.x * BN;

    // A tile load map: 128 rows x 8 cols = 256 float4, 1 per thread
    const int arow = tid >> 1;
    const int ac   = (tid & 1) * 4;
    // B tile load map: 8 rows x 128 cols = 256 float4, 1 per thread
    const int brow = tid >> 5;
    const int bc   = (tid & 31) * 4;

    // Compute map: 16x16 threads, each owns an 8x8 microtile
    const int rowb = (tid >> 4) * 8;
    const int colb = (tid & 15) * 8;

    float acc[8][8];
#pragma unroll
    for (int i = 0; i < 8; i++)
#pragma unroll
        for (int j = 0; j < 8; j++) acc[i][j] = 0.f;

    const float* Aptr = A + (size_t)(m0 + arow) * K + ac;
    const float* Bptr = B + (size_t)brow * N + n0 + bc;
    const bool bpred = (n0 + bc) < N;   // N % 4 == 0 -> whole float4 in/out

    // Prologue: load tile 0 into buffer 0
    {
        float4 av = *(const float4*)(Aptr);
        float4 bv = make_float4(0.f, 0.f, 0.f, 0.f);
        if (bpred) bv = *(const float4*)(Bptr);
        As[0][ac + 0][arow] = av.x;
        As[0][ac + 1][arow] = av.y;
        As[0][ac + 2][arow] = av.z;
        As[0][ac + 3][arow] = av.w;
        *(float4*)&Bs[0][brow][bc] = bv;
    }
    __syncthreads();

    int cur = 0;
    for (int kt = 0; kt < K; kt += BK) {
        const int nxt = cur ^ 1;
        const bool has_next = (kt + BK) < K;

        // Prefetch next tile into registers (issued before the FFMA block;
        // latency overlaps with compute below).
        float4 av2, bv2;
        if (has_next) {
            av2 = *(const float4*)(Aptr + kt + BK);
            bv2 = make_float4(0.f, 0.f, 0.f, 0.f);
            if (bpred) bv2 = *(const float4*)(Bptr + (size_t)(kt + BK) * N);
        }

        // Compute on current buffer
#pragma unroll
        for (int k = 0; k < BK; k++) {
            float a[8], b[8];
#pragma unroll
            for (int i = 0; i < 8; i++) a[i] = As[cur][k][rowb + i];
#pragma unroll
            for (int j = 0; j < 8; j++) b[j] = Bs[cur][k][colb + j];
#pragma unroll
            for (int i = 0; i < 8; i++)
#pragma unroll
                for (int j = 0; j < 8; j++)
                    acc[i][j] += a[i] * b[j];
        }

        // Commit prefetched tile to the alternate buffer
        if (has_next) {
            As[nxt][ac + 0][arow] = av2.x;
            As[nxt][ac + 1][arow] = av2.y;
            As[nxt][ac + 2][arow] = av2.z;
            As[nxt][ac + 3][arow] = av2.w;
            *(float4*)&Bs[nxt][brow][bc] = bv2;
        }
        __syncthreads();
        cur = nxt;
    }

#pragma unroll
    for (int i = 0; i < 8; i++) {
        const int m = m0 + rowb + i;   // M % 128 == 0 -> always valid
        float* crow = C + (size_t)m * N;
#pragma unroll
        for (int j = 0; j < 8; j += 4) {
            const int n = n0 + colb + j;
            if (n < N) {
                float4 o;
                o.x = acc[i][j + 0];
                o.y = acc[i][j + 1];
                o.z = acc[i][j + 2];
                o.w = acc[i][j + 3];
                if (bias) {
                    o.x += bias[n + 0];
                    o.y += bias[n + 1];
                    o.z += bias[n + 2];
                    o.w += bias[n + 3];
                }
                *(float4*)(crow + n) = o;
            }
        }
    }
}

// ---------------------------------------------------------------------------
// Tiny per-frame attention (24 joints x head-dim 6) over features [3,147)
// of each of the 8 heads. One block per frame, one warp per head.
// Lanes 0..23 each own one query row. Custom weighting chain:
//   row-0 updates done entirely in lane 0's registers,
//   column-0 updates via warp shuffles (sequential dependency preserved).
// ---------------------------------------------------------------------------
__global__ __launch_bounds__(256)
void tiny_attn_kernel()
{
    const int frame = blockIdx.x;
    const int warp  = threadIdx.x >> 5;   // head
    const int lane  = threadIdx.x & 31;

    __shared__ float ks[8][144];
    __shared__ float vs[8][144];

    const float* qptr = g_qk + (size_t)frame * QKW_N + warp * 147 + 3;
    const float* kptr = qptr + DHTOT;     // k half starts at 1176
    float*       vptr = g_v  + (size_t)frame * DHTOT + warp * 147 + 3;

    for (int i = lane; i < 144; i += 32) {
        ks[warp][i] = kptr[i];
        vs[warp][i] = vptr[i];
    }
    __syncwarp();

    float p[24];
    if (lane < 24) {
        float q[6];
#pragma unroll
        for (int d = 0; d < 6; d++) q[d] = qptr[lane * 6 + d];

        const float scale = 0.40824829046386307f;  // 1/sqrt(6)
        float mx = -CUDART_INF_F;
#pragma unroll
        for (int j = 0; j < 24; j++) {
            float s = 0.f;
#pragma unroll
            for (int d = 0; d < 6; d++) s += q[d] * ks[warp][j * 6 + d];
            s *= scale;
            p[j] = s;
            mx = fmaxf(mx, s);
        }
        float sum = 0.f;
#pragma unroll
        for (int j = 0; j < 24; j++) { p[j] = __expf(p[j] - mx); sum += p[j]; }
        const float inv = 1.f / sum;
#pragma unroll
        for (int j = 0; j < 24; j++) p[j] *= inv;
    } else {
#pragma unroll
        for (int j = 0; j < 24; j++) p[j] = 0.f;
    }

    // Row-0 chain: p[0][c] updates, all inside lane 0's registers.
    if (lane == 0) {
        p[6]  = (p[6]  + p[3])  * 0.5f;
        p[9]  = (p[9]  + p[6])  * 0.5f;
        p[12] = (p[12] + p[9])  * 0.5f;
        p[13] = (p[13] + p[9])  * 0.5f;
        p[14] = (p[14] + p[9])  * 0.5f;
        p[16] = (p[16] + p[13]) * 0.5f;
        p[17] = (p[17] + p[14]) * 0.5f;
        p[15] = (p[15] + p[12]) * 0.5f;
    }

    // Column-0 chain: p[r][0] lives in lane r. Sequential averages via shuffles.
    {
        float c0 = p[0];
        float t;
        t = __shfl_sync(0xFFFFFFFFu, c0, 3);
        if (lane == 6) c0 = (c0 + t) * 0.5f;
        t = __shfl_sync(0xFFFFFFFFu, c0, 6);
        if (lane == 9) c0 = (c0 + t) * 0.5f;
        t = __shfl_sync(0xFFFFFFFFu, c0, 9);
        if (lane >= 12 && lane <= 14) c0 = (c0 + t) * 0.5f;
        float t12 = __shfl_sync(0xFFFFFFFFu, c0, 12);
        float t13 = __shfl_sync(0xFFFFFFFFu, c0, 13);
        float t14 = __shfl_sync(0xFFFFFFFFu, c0, 14);
        if (lane == 16) c0 = (c0 + t13) * 0.5f;
        if (lane == 17) c0 = (c0 + t14) * 0.5f;
        if (lane == 15) c0 = (c0 + t12) * 0.5f;
        p[0] = c0;
    }

    if (lane < 24) {
        float out[6];
#pragma unroll
        for (int d = 0; d < 6; d++) {
            float s = 0.f;
#pragma unroll
            for (int j = 0; j < 24; j++) s += p[j] * vs[warp][j * 6 + d];
            out[d] = s;
        }
#pragma unroll
        for (int d = 0; d < 6; d++) vptr[lane * 6 + d] = out[d];
    }
}

// ---------------------------------------------------------------------------
// Launch: inputs per metadata order:
//   0 query, 1 key (unused by reference!), 2 value, 3 qk_w, 4 v_w, 5 lin_w, 6 lin_b
// ---------------------------------------------------------------------------
extern "C" void kernel_launch(void* const* d_in, const int* in_sizes, int n_in,
                              void* d_out, int out_size)
{
    const float* query = (const float*)d_in[0];
    const float* value = (const float*)d_in[2];
    const float* qk_w  = (const float*)d_in[3];
    const float* v_w   = (const float*)d_in[4];
    const float* lin_w = (const float*)d_in[5];
    const float* lin_b = (const float*)d_in[6];
    float* out = (float*)d_out;

    float *qk, *v;
    cudaGetSymbolAddress((void**)&qk, g_qk);
    cudaGetSymbolAddress((void**)&v,  g_v);

    dim3 blk(256);

    // QK = query @ qk_w   [16384,512] x [512,2352]
    sgemm_kernel<<<dim3((QKW_N + 127) / 128, FRAMES / 128), blk>>>(
        query, qk_w, qk, nullptr, FRAMES, QKW_N, DMODEL);

    // V = value @ v_w     [16384,512] x [512,1176]
    sgemm_kernel<<<dim3((DHTOT + 127) / 128, FRAMES / 128), blk>>>(
        value, v_w, v, nullptr, FRAMES, DHTOT, DMODEL);

    // Per-frame tiny attention, updates g_v[..., 3:147) per head in place
    tiny_attn_kernel<<<FRAMES, 256>>>();

    // out = V' @ lin_w + lin_b   [16384,1176] x [1176,512]
    sgemm_kernel<<<dim3((DMODEL + 127) / 128, FRAMES / 128), blk>>>(
        v, lin_w, out, lin_b, FRAMES, DMODEL, DHTOT);
}

// round 4
// speedup vs baseline: 2.4150x; 2.4150x over previous
#include <cuda_runtime.h>
#include <cuda_bf16.h>
#include <math_constants.h>
#include <cstdint>

// ---------------------------------------------------------------------------
// Problem constants
// ---------------------------------------------------------------------------
#define FRAMES 16384        // B*N = 32*512
#define DMODEL 512
#define DHTOT  1176         // DEPTH*HEADS = 147*8
#define QKW_N  2352         // 2*DHTOT

#define K3_PROJ 1536        // 3*512  (split-bf16 expanded K for proj GEMMs)
#define K3_OUT  3584        // 3*1176 = 3528 padded to 56*64

// ---------------------------------------------------------------------------
// Scratch (device globals; no cudaMalloc allowed)
// ---------------------------------------------------------------------------
__device__ float g_qk[(size_t)FRAMES * QKW_N];            // q|k projection fp32
__device__ float g_v [(size_t)FRAMES * DHTOT];            // v projection fp32
__device__ __nv_bfloat16 g_Aq [(size_t)FRAMES * K3_PROJ]; // split(query)
__device__ __nv_bfloat16 g_Av [(size_t)FRAMES * K3_OUT];  // split(value)/split(v')
__device__ __nv_bfloat16 g_Bqk[(size_t)QKW_N  * K3_PROJ]; // split(qk_w^T)
__device__ __nv_bfloat16 g_Bv [(size_t)DHTOT  * K3_PROJ]; // split(v_w^T)
__device__ __nv_bfloat16 g_Bl [(size_t)DMODEL * K3_OUT];  // split(lin_w^T)

// ---------------------------------------------------------------------------
// PTX helpers (family-common: cp.async / ldmatrix / mma.sync only)
// ---------------------------------------------------------------------------
__device__ __forceinline__ uint32_t smem_u32(const void* p) {
    uint32_t a;
    asm("{ .reg .u64 t; cvta.to.shared.u64 t, %1; cvt.u32.u64 %0, t; }"
        : "=r"(a) : "l"(p));
    return a;
}

__device__ __forceinline__ void cp16(uint32_t dst, const void* src, bool pred) {
    asm volatile("cp.async.cg.shared.global [%0], [%1], 16, %2;"
                 :: "r"(dst), "l"(src), "r"(pred ? 16u : 0u) : "memory");
}
__device__ __forceinline__ void cp_commit() {
    asm volatile("cp.async.commit_group;" ::: "memory");
}

__device__ __forceinline__ void ldsm4(uint32_t* r, uint32_t addr) {
    asm volatile("ldmatrix.sync.aligned.m8n8.x4.shared.b16 {%0,%1,%2,%3}, [%4];"
                 : "=r"(r[0]), "=r"(r[1]), "=r"(r[2]), "=r"(r[3]) : "r"(addr));
}

__device__ __forceinline__ void mma16816(float* d, const uint32_t* a,
                                         uint32_t b0, uint32_t b1) {
    asm volatile(
        "mma.sync.aligned.m16n8k16.row.col.f32.bf16.bf16.f32 "
        "{%0,%1,%2,%3}, {%4,%5,%6,%7}, {%8,%9}, {%0,%1,%2,%3};"
        : "+f"(d[0]), "+f"(d[1]), "+f"(d[2]), "+f"(d[3])
        : "r"(a[0]), "r"(a[1]), "r"(a[2]), "r"(a[3]), "r"(b0), "r"(b1));
}

__device__ __forceinline__ uint32_t sw128(uint32_t off) {
    return off ^ ((off >> 3) & 0x70);
}

// ---------------------------------------------------------------------------
// Split-bf16 HMMA GEMM: C[M,N] = A'[M,K3] x B'[N,K3]^T (+ bias)
// CTA tile 128x128, BK=64 bf16, 8 warps (2x4) each 64x32, double-buffered
// cp.async. grid = (ceil(N/128), M/128), 256 threads.
// ---------------------------------------------------------------------------
#define GEMM_SMEM 65536   // 2 bufs x (A 16KB + B 16KB)

__global__ __launch_bounds__(256, 2)
void gemm_tc(const __nv_bfloat16* __restrict__ A, const __nv_bfloat16* __restrict__ Bw,
             float* __restrict__ C, const float* __restrict__ bias,
             int Kt, int K3, int N)
{
    extern __shared__ char smem[];
    const uint32_t sb = smem_u32(smem);
    const int tid  = threadIdx.x;
    const int wid  = tid >> 5;
    const int lane = tid & 31;
    const int m0 = blockIdx.y * 128;
    const int n0 = blockIdx.x * 128;
    const int wm = wid >> 2;   // 0..1 -> rows wm*64
    const int wn = wid & 3;    // 0..3 -> cols wn*32

    // global load map: f = i*256+tid ; row = f>>3 ; ch = f&7 (16B chunks)
    const int grow = tid >> 3;         // base row for i=0 (rows 0..31 step per i: +32)
    const int gch  = tid & 7;
    const uint32_t sdst = sw128((uint32_t)(grow * 128 + gch * 16));

    float acc[4][4][4];
#pragma unroll
    for (int a = 0; a < 4; a++)
#pragma unroll
        for (int b = 0; b < 4; b++)
#pragma unroll
            for (int c = 0; c < 4; c++) acc[a][b][c] = 0.f;

    // ---- tile loader ----
    auto load_tile = [&](int it) {
        const int buf = it & 1;
        const uint32_t da = sb + buf * 32768u;
        const uint32_t db = da + 16384u;
        const __nv_bfloat16* Ag = A + (size_t)(m0 + grow) * K3 + it * 64 + gch * 8;
        const __nv_bfloat16* Bg = Bw + it * 64 + gch * 8;
#pragma unroll
        for (int i = 0; i < 4; i++) {
            cp16(da + sdst + i * 4096u, Ag + (size_t)i * 32 * K3, true);
        }
#pragma unroll
        for (int i = 0; i < 4; i++) {
            const int n = n0 + grow + i * 32;
            const bool p = n < N;
            cp16(db + sdst + i * 4096u,
                 Bg + (size_t)(p ? n : 0) * K3, p);
        }
        cp_commit();
    };

    load_tile(0);
    if (Kt > 1) load_tile(1);

    // ldmatrix lane address components (pre-swizzle bases; k-step via XOR)
    const int a_lrow = lane & 15;
    const uint32_t a_kh = (lane & 16) ? 16u : 0u;
    const int b_lrow = (lane & 7) + ((lane & 16) ? 8 : 0);
    const uint32_t b_kh = (lane & 8) ? 16u : 0u;

    for (int it = 0; it < Kt; it++) {
        if (it + 1 < Kt) asm volatile("cp.async.wait_group 1;" ::: "memory");
        else             asm volatile("cp.async.wait_group 0;" ::: "memory");
        __syncthreads();

        const int buf = it & 1;
        const uint32_t da = sb + buf * 32768u;
        const uint32_t db = da + 16384u;

        // per-buffer ldmatrix base addresses
        uint32_t aaddr[4], baddr[2];
#pragma unroll
        for (int mt = 0; mt < 4; mt++)
            aaddr[mt] = da + sw128((uint32_t)((wm * 64 + mt * 16 + a_lrow) * 128) + a_kh);
#pragma unroll
        for (int np = 0; np < 2; np++)
            baddr[np] = db + sw128((uint32_t)((wn * 32 + np * 16 + b_lrow) * 128) + b_kh);

#pragma unroll
        for (int kc = 0; kc < 4; kc++) {
            const uint32_t kx = kc * 32u;
            uint32_t af[4][4];
#pragma unroll
            for (int mt = 0; mt < 4; mt++) ldsm4(af[mt], aaddr[mt] ^ kx);
            uint32_t bf[2][4];
#pragma unroll
            for (int np = 0; np < 2; np++) ldsm4(bf[np], baddr[np] ^ kx);
#pragma unroll
            for (int mt = 0; mt < 4; mt++)
#pragma unroll
                for (int nt = 0; nt < 4; nt++)
                    mma16816(acc[mt][nt], af[mt],
                             bf[nt >> 1][(nt & 1) * 2 + 0],
                             bf[nt >> 1][(nt & 1) * 2 + 1]);
        }

        __syncthreads();
        if (it + 2 < Kt) load_tile(it + 2);
    }

    // ---- epilogue: direct predicated stores ----
    const int erow = m0 + wm * 64 + (lane >> 2);
    const int ecol0 = n0 + wn * 32 + (lane & 3) * 2;
#pragma unroll
    for (int mt = 0; mt < 4; mt++) {
#pragma unroll
        for (int nt = 0; nt < 4; nt++) {
            const int col = ecol0 + nt * 8;
            if (col < N) {
                float bx = 0.f, by = 0.f;
                if (bias) { bx = bias[col]; by = bias[col + 1]; }
                float2 v0 = make_float2(acc[mt][nt][0] + bx, acc[mt][nt][1] + by);
                float2 v1 = make_float2(acc[mt][nt][2] + bx, acc[mt][nt][3] + by);
                *(float2*)(C + (size_t)(erow + mt * 16) * N + col) = v0;
                *(float2*)(C + (size_t)(erow + mt * 16 + 8) * N + col) = v1;
            }
        }
    }
}

// ---------------------------------------------------------------------------
// Split fp32 -> [hi | lo | hi] bf16 along K (A operands, M-major rows)
// ---------------------------------------------------------------------------
__global__ void convertA_kernel(const float* __restrict__ in, __nv_bfloat16* __restrict__ out,
                                int K, int K3, int total)
{
    const int idx = blockIdx.x * 256 + threadIdx.x;
    if (idx >= total) return;
    const int cpr = K3 >> 3;
    const int m = idx / cpr;
    const int k3 = (idx - m * cpr) << 3;
    __align__(16) __nv_bfloat16 o[8];
    if (k3 >= 3 * K) {
#pragma unroll
        for (int i = 0; i < 8; i++) o[i] = __float2bfloat16(0.f);
    } else {
        const int s = k3 / K;
        const int kk = k3 - s * K;
        const float* src = in + (size_t)m * K + kk;
#pragma unroll
        for (int i = 0; i < 8; i++) {
            const float x = src[i];
            const __nv_bfloat16 hi = __float2bfloat16(x);
            o[i] = (s == 1) ? __float2bfloat16(x - __bfloat162float(hi)) : hi;
        }
    }
    *(uint4*)(out + (size_t)m * K3 + k3) = *(const uint4*)o;
}

// ---------------------------------------------------------------------------
// Split + transpose weights: in [K,N] fp32 -> out [N,K3] bf16 = [hi | hi | lo]
// ---------------------------------------------------------------------------
__global__ void convertB_kernel(const float* __restrict__ in, __nv_bfloat16* __restrict__ out,
                                int K, int K3, int N, int total)
{
    const int idx = blockIdx.x * 256 + threadIdx.x;
    if (idx >= total) return;
    const int n = idx % N;
    const int c = idx / N;
    const int k3 = c << 3;
    __align__(16) __nv_bfloat16 o[8];
    if (k3 >= 3 * K) {
#pragma unroll
        for (int i = 0; i < 8; i++) o[i] = __float2bfloat16(0.f);
    } else {
        const int s = k3 / K;
        const int kk = k3 - s * K;
#pragma unroll
        for (int i = 0; i < 8; i++) {
            const float x = in[(size_t)(kk + i) * N + n];
            const __nv_bfloat16 hi = __float2bfloat16(x);
            o[i] = (s == 2) ? __float2bfloat16(x - __bfloat162float(hi)) : hi;
        }
    }
    *(uint4*)(out + (size_t)n * K3 + k3) = *(const uint4*)o;
}

// ---------------------------------------------------------------------------
// Tiny per-frame attention (24 joints x 6) on features [3,147) of each head.
// One block per frame, one warp per head.
// ---------------------------------------------------------------------------
__global__ __launch_bounds__(256)
void tiny_attn_kernel()
{
    const int frame = blockIdx.x;
    const int warp  = threadIdx.x >> 5;
    const int lane  = threadIdx.x & 31;

    __shared__ float ks[8][144];
    __shared__ float vs[8][144];

    const float* qptr = g_qk + (size_t)frame * QKW_N + warp * 147 + 3;
    const float* kptr = qptr + DHTOT;
    float*       vptr = g_v  + (size_t)frame * DHTOT + warp * 147 + 3;

    for (int i = lane; i < 144; i += 32) {
        ks[warp][i] = kptr[i];
        vs[warp][i] = vptr[i];
    }
    __syncwarp();

    float p[24];
    if (lane < 24) {
        float q[6];
#pragma unroll
        for (int d = 0; d < 6; d++) q[d] = qptr[lane * 6 + d];
        const float scale = 0.40824829046386307f;
        float mx = -CUDART_INF_F;
#pragma unroll
        for (int j = 0; j < 24; j++) {
            float s = 0.f;
#pragma unroll
            for (int d = 0; d < 6; d++) s += q[d] * ks[warp][j * 6 + d];
            s *= scale;
            p[j] = s;
            mx = fmaxf(mx, s);
        }
        float sum = 0.f;
#pragma unroll
        for (int j = 0; j < 24; j++) { p[j] = __expf(p[j] - mx); sum += p[j]; }
        const float inv = 1.f / sum;
#pragma unroll
        for (int j = 0; j < 24; j++) p[j] *= inv;
    } else {
#pragma unroll
        for (int j = 0; j < 24; j++) p[j] = 0.f;
    }

    if (lane == 0) {
        p[6]  = (p[6]  + p[3])  * 0.5f;
        p[9]  = (p[9]  + p[6])  * 0.5f;
        p[12] = (p[12] + p[9])  * 0.5f;
        p[13] = (p[13] + p[9])  * 0.5f;
        p[14] = (p[14] + p[9])  * 0.5f;
        p[16] = (p[16] + p[13]) * 0.5f;
        p[17] = (p[17] + p[14]) * 0.5f;
        p[15] = (p[15] + p[12]) * 0.5f;
    }

    {
        float c0 = p[0];
        float t;
        t = __shfl_sync(0xFFFFFFFFu, c0, 3);
        if (lane == 6) c0 = (c0 + t) * 0.5f;
        t = __shfl_sync(0xFFFFFFFFu, c0, 6);
        if (lane == 9) c0 = (c0 + t) * 0.5f;
        t = __shfl_sync(0xFFFFFFFFu, c0, 9);
        if (lane >= 12 && lane <= 14) c0 = (c0 + t) * 0.5f;
        float t12 = __shfl_sync(0xFFFFFFFFu, c0, 12);
        float t13 = __shfl_sync(0xFFFFFFFFu, c0, 13);
        float t14 = __shfl_sync(0xFFFFFFFFu, c0, 14);
        if (lane == 16) c0 = (c0 + t13) * 0.5f;
        if (lane == 17) c0 = (c0 + t14) * 0.5f;
        if (lane == 15) c0 = (c0 + t12) * 0.5f;
        p[0] = c0;
    }

    if (lane < 24) {
        float out[6];
#pragma unroll
        for (int d = 0; d < 6; d++) {
            float s = 0.f;
#pragma unroll
            for (int j = 0; j < 24; j++) s += p[j] * vs[warp][j * 6 + d];
            out[d] = s;
        }
#pragma unroll
        for (int d = 0; d < 6; d++) vptr[lane * 6 + d] = out[d];
    }
}

// ---------------------------------------------------------------------------
// Launch. Inputs: 0 query, 1 key (unused by ref), 2 value, 3 qk_w, 4 v_w,
//                 5 lin_w, 6 lin_b
// ---------------------------------------------------------------------------
extern "C" void kernel_launch(void* const* d_in, const int* in_sizes, int n_in,
                              void* d_out, int out_size)
{
    const float* query = (const float*)d_in[0];
    const float* value = (const float*)d_in[2];
    const float* qk_w  = (const float*)d_in[3];
    const float* v_w   = (const float*)d_in[4];
    const float* lin_w = (const float*)d_in[5];
    const float* lin_b = (const float*)d_in[6];
    float* out = (float*)d_out;

    cudaFuncSetAttribute(gemm_tc, cudaFuncAttributeMaxDynamicSharedMemorySize, GEMM_SMEM);

    float *qk, *v;
    __nv_bfloat16 *Aq, *Av, *Bqk, *Bv, *Bl;
    cudaGetSymbolAddress((void**)&qk,  g_qk);
    cudaGetSymbolAddress((void**)&v,   g_v);
    cudaGetSymbolAddress((void**)&Aq,  g_Aq);
    cudaGetSymbolAddress((void**)&Av,  g_Av);
    cudaGetSymbolAddress((void**)&Bqk, g_Bqk);
    cudaGetSymbolAddress((void**)&Bv,  g_Bv);
    cudaGetSymbolAddress((void**)&Bl,  g_Bl);

    // 1) split conversions for projection GEMMs
    {
        int totA = FRAMES * (K3_PROJ / 8);
        convertA_kernel<<<(totA + 255) / 256, 256>>>(query, Aq, DMODEL, K3_PROJ, totA);
        convertA_kernel<<<(totA + 255) / 256, 256>>>(value, Av, DMODEL, K3_PROJ, totA);
        int totB1 = QKW_N * (K3_PROJ / 8);
        convertB_kernel<<<(totB1 + 255) / 256, 256>>>(qk_w, Bqk, DMODEL, K3_PROJ, QKW_N, totB1);
        int totB2 = DHTOT * (K3_PROJ / 8);
        convertB_kernel<<<(totB2 + 255) / 256, 256>>>(v_w, Bv, DMODEL, K3_PROJ, DHTOT, totB2);
    }

    // 2) QK = query @ qk_w  [16384 x 2352]
    gemm_tc<<<dim3((QKW_N + 127) / 128, FRAMES / 128), 256, GEMM_SMEM>>>(
        Aq, Bqk, qk, nullptr, K3_PROJ / 64, K3_PROJ, QKW_N);

    // 3) V = value @ v_w    [16384 x 1176]
    gemm_tc<<<dim3((DHTOT + 127) / 128, FRAMES / 128), 256, GEMM_SMEM>>>(
        Av, Bv, v, nullptr, K3_PROJ / 64, K3_PROJ, DHTOT);

    // 4) tiny attention updates g_v[..., 3:147) per head in place
    tiny_attn_kernel<<<FRAMES, 256>>>();

    // 5) split conversions for output GEMM
    {
        int totA = FRAMES * (K3_OUT / 8);
        convertA_kernel<<<(totA + 255) / 256, 256>>>(v, Av, DHTOT, K3_OUT, totA);
        int totB = DMODEL * (K3_OUT / 8);
        convertB_kernel<<<(totB + 255) / 256, 256>>>(lin_w, Bl, DHTOT, K3_OUT, DMODEL, totB);
    }

    // 6) out = V' @ lin_w + lin_b  [16384 x 512]
    gemm_tc<<<dim3((DMODEL + 127) / 128, FRAMES / 128), 256, GEMM_SMEM>>>(
        Av, Bl, out, lin_b, K3_OUT / 64, K3_OUT, DMODEL);
}